// round 1
// baseline (speedup 1.0000x reference)
#include <cuda_runtime.h>
#include <math.h>

#define N_NODES 50000
#define N_EDGES 800000
#define F_DIM   64
#define AVG_D_LOG 2.833f
#define EPS_STD 1e-5f
#define EPS_BN  1e-5f

// ---------------- device scratch (allocation-free rule: __device__ globals) --
__device__ int   g_deg[N_NODES];
__device__ int   g_off[N_NODES];
__device__ int   g_cursor[N_NODES];
__device__ int   g_esrc[N_EDGES];
__device__ float g_agg[(size_t)N_NODES * 256];   // [mean|max|min|std] per node
__device__ float g_c1[N_NODES];                  // amplification scale
__device__ float g_c2[N_NODES];                  // attenuation scale
__device__ float g_x[(size_t)N_NODES * F_DIM];   // posttrans output (pre-BN)
__device__ float g_colsum[F_DIM];
__device__ float g_colsq[F_DIM];

// ---------------- K0: zero the per-call accumulators ------------------------
__global__ void k_zero() {
    int i = blockIdx.x * blockDim.x + threadIdx.x;
    if (i < N_NODES) g_deg[i] = 0;
    if (i < F_DIM) { g_colsum[i] = 0.f; g_colsq[i] = 0.f; }
}

// ---------------- K1: degree histogram ---------------------------------------
__global__ void k_hist(const int* __restrict__ dst) {
    int e = blockIdx.x * blockDim.x + threadIdx.x;
    if (e < N_EDGES) atomicAdd(&g_deg[dst[e]], 1);
}

// ---------------- K2: single-block exclusive scan over 50000 degrees --------
__global__ void k_scan() {
    __shared__ int s[1024];
    __shared__ int carry;
    int tid = threadIdx.x;
    if (tid == 0) carry = 0;
    __syncthreads();
    for (int base = 0; base < N_NODES; base += 1024) {
        int i = base + tid;
        int v = (i < N_NODES) ? g_deg[i] : 0;
        s[tid] = v;
        __syncthreads();
        #pragma unroll
        for (int off = 1; off < 1024; off <<= 1) {
            int t = (tid >= off) ? s[tid - off] : 0;
            __syncthreads();
            s[tid] += t;
            __syncthreads();
        }
        if (i < N_NODES) {
            int ex = s[tid] - v + carry;
            g_off[i] = ex;
            g_cursor[i] = ex;
        }
        __syncthreads();
        if (tid == 0) carry += s[1023];
        __syncthreads();
    }
}

// ---------------- K3: scatter edges into CSR order --------------------------
__global__ void k_scatter(const int* __restrict__ src, const int* __restrict__ dst) {
    int e = blockIdx.x * blockDim.x + threadIdx.x;
    if (e < N_EDGES) {
        int pos = atomicAdd(&g_cursor[dst[e]], 1);
        g_esrc[pos] = src[e];
    }
}

// ---------------- K4: warp-per-node aggregation (mean/max/min/std) ----------
__global__ void k_agg(const float* __restrict__ h) {
    int warp = (blockIdx.x * blockDim.x + threadIdx.x) >> 5;
    int lane = threadIdx.x & 31;
    if (warp >= N_NODES) return;

    int start = g_off[warp];
    int d = g_deg[warp];

    float s0 = 0.f, s1 = 0.f, q0 = 0.f, q1 = 0.f;
    float mx0 = -3.402823466e38f, mx1 = -3.402823466e38f;
    float mn0 =  3.402823466e38f, mn1 =  3.402823466e38f;

    for (int e = 0; e < d; e++) {
        int sid = g_esrc[start + e];
        float v0 = h[sid * 64 + lane];
        float v1 = h[sid * 64 + 32 + lane];
        s0 += v0; s1 += v1;
        q0 = fmaf(v0, v0, q0); q1 = fmaf(v1, v1, q1);
        mx0 = fmaxf(mx0, v0); mx1 = fmaxf(mx1, v1);
        mn0 = fminf(mn0, v0); mn1 = fminf(mn1, v1);
    }

    float* base = g_agg + (size_t)warp * 256;
    if (d > 0) {
        float inv = 1.0f / (float)d;
        float mean0 = s0 * inv, mean1 = s1 * inv;
        float var0 = fmaxf(q0 * inv - mean0 * mean0, 0.f);
        float var1 = fmaxf(q1 * inv - mean1 * mean1, 0.f);
        float std0 = sqrtf(var0 + EPS_STD);
        float std1 = sqrtf(var1 + EPS_STD);
        base[lane]        = mean0; base[32 + lane]  = mean1;
        base[64 + lane]   = mx0;   base[96 + lane]  = mx1;
        base[128 + lane]  = mn0;   base[160 + lane] = mn1;
        base[192 + lane]  = std0;  base[224 + lane] = std1;
        if (lane == 0) {
            float logD = logf((float)d + 1.0f);
            g_c1[warp] = logD / AVG_D_LOG;
            g_c2[warp] = AVG_D_LOG / fmaxf(logD, 1e-12f);
        }
    } else {
        base[lane] = 0.f;       base[32 + lane] = 0.f;
        base[64 + lane] = 0.f;  base[96 + lane] = 0.f;
        base[128 + lane] = 0.f; base[160 + lane] = 0.f;
        base[192 + lane] = 0.f; base[224 + lane] = 0.f;
        if (lane == 0) { g_c1[warp] = 0.f; g_c2[warp] = 0.f; }
    }
}

// ---------------- K5: fused GEMM  x = agg@W1 + c1*(agg@W2) + c2*(agg@W3) + b
// A = g_agg [N,256], W = [768,64] split in 3 panels of [256,64].
// Block tile: 64 nodes x 64 cols (x3 panels). 256 threads, 4x4 outputs each.
#define BM 64
#define KC 32
__global__ void __launch_bounds__(256) k_gemm(const float* __restrict__ W,
                                              const float* __restrict__ b) {
    __shared__ __align__(16) float  sA[KC * 68];      // [k][m], row stride 68
    __shared__ float4 sW[3 * KC * 16];                // [p][k][j4]

    int t = threadIdx.x;
    int m0 = blockIdx.x * BM;
    int mi = t & 15;   // node quad index
    int ji = t >> 4;   // col  quad index (0..15)

    float acc[3][4][4];
    #pragma unroll
    for (int p = 0; p < 3; p++)
        #pragma unroll
        for (int a = 0; a < 4; a++)
            #pragma unroll
            for (int c = 0; c < 4; c++) acc[p][a][c] = 0.f;

    const float4* W4 = (const float4*)W;

    for (int kc = 0; kc < 256; kc += KC) {
        // load A tile: 64 m x 32 k, float4 along k
        #pragma unroll
        for (int it = 0; it < 2; it++) {
            int idx = t + it * 256;            // 0..511
            int m = idx >> 3;
            int k4 = idx & 7;
            int gm = m0 + m;
            float4 v = make_float4(0.f, 0.f, 0.f, 0.f);
            if (gm < N_NODES)
                v = *(const float4*)(g_agg + (size_t)gm * 256 + kc + k4 * 4);
            sA[(k4 * 4 + 0) * 68 + m] = v.x;
            sA[(k4 * 4 + 1) * 68 + m] = v.y;
            sA[(k4 * 4 + 2) * 68 + m] = v.z;
            sA[(k4 * 4 + 3) * 68 + m] = v.w;
        }
        // load W tiles: 3 panels x 32 k x 16 float4
        #pragma unroll
        for (int it = 0; it < 6; it++) {
            int idx = t + it * 256;            // 0..1535
            int p = idx >> 9;
            int rem = idx & 511;
            int k = rem >> 4;
            int j4 = rem & 15;
            sW[idx] = W4[(p * 256 + kc + k) * 16 + j4];
        }
        __syncthreads();

        #pragma unroll 8
        for (int k = 0; k < KC; k++) {
            float4 a4 = *(const float4*)(sA + k * 68 + mi * 4);
            float4 w0 = sW[k * 16 + ji];
            float4 w1 = sW[512 + k * 16 + ji];
            float4 w2 = sW[1024 + k * 16 + ji];
            float av[4] = {a4.x, a4.y, a4.z, a4.w};
            float w0v[4] = {w0.x, w0.y, w0.z, w0.w};
            float w1v[4] = {w1.x, w1.y, w1.z, w1.w};
            float w2v[4] = {w2.x, w2.y, w2.z, w2.w};
            #pragma unroll
            for (int mm = 0; mm < 4; mm++) {
                #pragma unroll
                for (int jj = 0; jj < 4; jj++) {
                    acc[0][mm][jj] = fmaf(av[mm], w0v[jj], acc[0][mm][jj]);
                    acc[1][mm][jj] = fmaf(av[mm], w1v[jj], acc[1][mm][jj]);
                    acc[2][mm][jj] = fmaf(av[mm], w2v[jj], acc[2][mm][jj]);
                }
            }
        }
        __syncthreads();
    }

    float4 bb = ((const float4*)b)[ji];
    float bv[4] = {bb.x, bb.y, bb.z, bb.w};
    #pragma unroll
    for (int mm = 0; mm < 4; mm++) {
        int gm = m0 + mi * 4 + mm;
        if (gm >= N_NODES) continue;
        float c1 = g_c1[gm];
        float c2 = g_c2[gm];
        float4 r;
        float rr[4];
        #pragma unroll
        for (int jj = 0; jj < 4; jj++)
            rr[jj] = acc[0][mm][jj] + c1 * acc[1][mm][jj] + c2 * acc[2][mm][jj] + bv[jj];
        r.x = rr[0]; r.y = rr[1]; r.z = rr[2]; r.w = rr[3];
        *(float4*)(g_x + (size_t)gm * 64 + ji * 4) = r;
    }
}

// ---------------- K6: column sums / sumsq for BatchNorm ---------------------
__global__ void k_colred() {
    __shared__ float ssum[4][64];
    __shared__ float ssq[4][64];
    int t = threadIdx.x;
    int j = t & 63;
    int g = t >> 6;   // 0..3
    float s = 0.f, q = 0.f;
    for (int n = blockIdx.x * 4 + g; n < N_NODES; n += gridDim.x * 4) {
        float v = g_x[(size_t)n * 64 + j];
        s += v;
        q = fmaf(v, v, q);
    }
    ssum[g][j] = s;
    ssq[g][j] = q;
    __syncthreads();
    if (g == 0) {
        s = ssum[0][j] + ssum[1][j] + ssum[2][j] + ssum[3][j];
        q = ssq[0][j] + ssq[1][j] + ssq[2][j] + ssq[3][j];
        atomicAdd(&g_colsum[j], s);
        atomicAdd(&g_colsq[j], q);
    }
}

// ---------------- K7: BN + ReLU + residual -----------------------------------
__global__ void k_final(const float* __restrict__ h,
                        const float* __restrict__ gamma,
                        const float* __restrict__ beta,
                        float* __restrict__ out) {
    int i = blockIdx.x * blockDim.x + threadIdx.x;
    if (i >= N_NODES * F_DIM) return;
    int j = i & 63;
    const float invN = 1.0f / (float)N_NODES;
    float mu = g_colsum[j] * invN;
    float var = g_colsq[j] * invN - mu * mu;
    float inv = rsqrtf(var + EPS_BN);
    float v = gamma[j] * (g_x[i] - mu) * inv + beta[j];
    out[i] = h[i] + fmaxf(v, 0.f);
}

// ---------------- launch ------------------------------------------------------
extern "C" void kernel_launch(void* const* d_in, const int* in_sizes, int n_in,
                              void* d_out, int out_size) {
    const float* h     = (const float*)d_in[0];
    const int*   src   = (const int*)d_in[1];
    const int*   dst   = (const int*)d_in[2];
    const float* W     = (const float*)d_in[3];
    const float* b     = (const float*)d_in[4];
    const float* gamma = (const float*)d_in[5];
    const float* beta  = (const float*)d_in[6];
    float* out = (float*)d_out;

    k_zero<<<(N_NODES + 255) / 256, 256>>>();
    k_hist<<<(N_EDGES + 255) / 256, 256>>>(dst);
    k_scan<<<1, 1024>>>();
    k_scatter<<<(N_EDGES + 255) / 256, 256>>>(src, dst);
    k_agg<<<(N_NODES + 7) / 8, 256>>>(h);                 // 8 warps/block, warp per node
    k_gemm<<<(N_NODES + BM - 1) / BM, 256>>>(W, b);       // 782 blocks
    k_colred<<<128, 256>>>();
    k_final<<<(N_NODES * F_DIM + 255) / 256, 256>>>(h, gamma, beta, out);
}

// round 2
// speedup vs baseline: 1.3432x; 1.3432x over previous
#include <cuda_runtime.h>
#include <math.h>

#define N_NODES 50000
#define N_EDGES 800000
#define F_DIM   64
#define AVG_D_LOG 2.833f
#define EPS_STD 1e-5f
#define EPS_BN  1e-5f
#define NB 196   // ceil(50000/256)

// ---------------- device scratch ---------------------------------------------
__device__ int   g_deg[N_NODES];
__device__ int   g_off[N_NODES];
__device__ int   g_cursor[N_NODES];
__device__ int   g_esrc[N_EDGES];
__device__ int   g_bsum[NB];
__device__ int   g_boff[NB];
__device__ float g_agg[(size_t)N_NODES * 256];   // [mean|max|min|std] per node
__device__ float g_c1[N_NODES];
__device__ float g_c2[N_NODES];
__device__ float g_x[(size_t)N_NODES * F_DIM];
__device__ float g_colsum[F_DIM];
__device__ float g_colsq[F_DIM];

// ---------------- f32x2 helpers ----------------------------------------------
__device__ __forceinline__ unsigned long long pack2(float x) {
    unsigned long long r;
    asm("mov.b64 %0, {%1, %1};" : "=l"(r) : "f"(x));
    return r;
}
__device__ __forceinline__ void ffma2(unsigned long long& d,
                                      unsigned long long a,
                                      unsigned long long b) {
    asm("fma.rn.f32x2 %0, %1, %2, %0;" : "+l"(d) : "l"(a), "l"(b));
}
__device__ __forceinline__ float lo32(unsigned long long v) {
    return __uint_as_float((unsigned)v);
}
__device__ __forceinline__ float hi32(unsigned long long v) {
    return __uint_as_float((unsigned)(v >> 32));
}

// ---------------- K0: zero ----------------------------------------------------
__global__ void k_zero() {
    int i = blockIdx.x * blockDim.x + threadIdx.x;
    if (i < N_NODES) g_deg[i] = 0;
    if (i < F_DIM) { g_colsum[i] = 0.f; g_colsq[i] = 0.f; }
}

// ---------------- K1: degree histogram ----------------------------------------
__global__ void k_hist(const int* __restrict__ dst) {
    int e = blockIdx.x * blockDim.x + threadIdx.x;
    if (e < N_EDGES) atomicAdd(&g_deg[dst[e]], 1);
}

// ---------------- K2a: per-block sums ------------------------------------------
__global__ void k_part() {
    __shared__ int s[256];
    int t = threadIdx.x;
    int i = blockIdx.x * 256 + t;
    int v = (i < N_NODES) ? g_deg[i] : 0;
    s[t] = v;
    __syncthreads();
    #pragma unroll
    for (int off = 128; off > 0; off >>= 1) {
        if (t < off) s[t] += s[t + off];
        __syncthreads();
    }
    if (t == 0) g_bsum[blockIdx.x] = s[0];
}

// ---------------- K2b: scan of 196 block sums (one small block) ----------------
__global__ void k_scan2() {
    __shared__ int s[256];
    int t = threadIdx.x;
    int v = (t < NB) ? g_bsum[t] : 0;
    s[t] = v;
    __syncthreads();
    #pragma unroll
    for (int off = 1; off < 256; off <<= 1) {
        int x = (t >= off) ? s[t - off] : 0;
        __syncthreads();
        s[t] += x;
        __syncthreads();
    }
    if (t < NB) g_boff[t] = s[t] - v;   // exclusive
}

// ---------------- K2c: local scan + global offset ------------------------------
__global__ void k_off() {
    __shared__ int s[256];
    int t = threadIdx.x;
    int i = blockIdx.x * 256 + t;
    int v = (i < N_NODES) ? g_deg[i] : 0;
    s[t] = v;
    __syncthreads();
    #pragma unroll
    for (int off = 1; off < 256; off <<= 1) {
        int x = (t >= off) ? s[t - off] : 0;
        __syncthreads();
        s[t] += x;
        __syncthreads();
    }
    if (i < N_NODES) {
        int ex = s[t] - v + g_boff[blockIdx.x];
        g_off[i] = ex;
        g_cursor[i] = ex;
    }
}

// ---------------- K3: scatter edges into CSR order -----------------------------
__global__ void k_scatter(const int* __restrict__ src, const int* __restrict__ dst) {
    int e = blockIdx.x * blockDim.x + threadIdx.x;
    if (e < N_EDGES) {
        int pos = atomicAdd(&g_cursor[dst[e]], 1);
        g_esrc[pos] = src[e];
    }
}

// ---------------- K4: warp-per-node aggregation --------------------------------
__global__ void k_agg(const float* __restrict__ h) {
    int warp = (blockIdx.x * blockDim.x + threadIdx.x) >> 5;
    int lane = threadIdx.x & 31;
    if (warp >= N_NODES) return;

    int start = g_off[warp];
    int d = g_deg[warp];

    const float2* h2 = (const float2*)h;   // lane owns cols 2*lane, 2*lane+1

    float s0 = 0.f, s1 = 0.f, q0 = 0.f, q1 = 0.f;
    float mx0 = -3.402823466e38f, mx1 = -3.402823466e38f;
    float mn0 =  3.402823466e38f, mn1 =  3.402823466e38f;

    int e = 0;
    for (; e + 2 <= d; e += 2) {
        int sa = g_esrc[start + e];
        int sb = g_esrc[start + e + 1];
        float2 va = h2[sa * 32 + lane];
        float2 vb = h2[sb * 32 + lane];
        s0 += va.x; s1 += va.y;
        q0 = fmaf(va.x, va.x, q0); q1 = fmaf(va.y, va.y, q1);
        mx0 = fmaxf(mx0, va.x); mx1 = fmaxf(mx1, va.y);
        mn0 = fminf(mn0, va.x); mn1 = fminf(mn1, va.y);
        s0 += vb.x; s1 += vb.y;
        q0 = fmaf(vb.x, vb.x, q0); q1 = fmaf(vb.y, vb.y, q1);
        mx0 = fmaxf(mx0, vb.x); mx1 = fmaxf(mx1, vb.y);
        mn0 = fminf(mn0, vb.x); mn1 = fminf(mn1, vb.y);
    }
    if (e < d) {
        int sa = g_esrc[start + e];
        float2 va = h2[sa * 32 + lane];
        s0 += va.x; s1 += va.y;
        q0 = fmaf(va.x, va.x, q0); q1 = fmaf(va.y, va.y, q1);
        mx0 = fmaxf(mx0, va.x); mx1 = fmaxf(mx1, va.y);
        mn0 = fminf(mn0, va.x); mn1 = fminf(mn1, va.y);
    }

    float* base = g_agg + (size_t)warp * 256;
    if (d > 0) {
        float inv = 1.0f / (float)d;
        float mean0 = s0 * inv, mean1 = s1 * inv;
        float var0 = fmaxf(q0 * inv - mean0 * mean0, 0.f);
        float var1 = fmaxf(q1 * inv - mean1 * mean1, 0.f);
        float std0 = sqrtf(var0 + EPS_STD);
        float std1 = sqrtf(var1 + EPS_STD);
        *(float2*)(base +       2 * lane) = make_float2(mean0, mean1);
        *(float2*)(base +  64 + 2 * lane) = make_float2(mx0, mx1);
        *(float2*)(base + 128 + 2 * lane) = make_float2(mn0, mn1);
        *(float2*)(base + 192 + 2 * lane) = make_float2(std0, std1);
        if (lane == 0) {
            float logD = logf((float)d + 1.0f);
            g_c1[warp] = logD / AVG_D_LOG;
            g_c2[warp] = AVG_D_LOG / fmaxf(logD, 1e-12f);
        }
    } else {
        float2 z = make_float2(0.f, 0.f);
        *(float2*)(base +       2 * lane) = z;
        *(float2*)(base +  64 + 2 * lane) = z;
        *(float2*)(base + 128 + 2 * lane) = z;
        *(float2*)(base + 192 + 2 * lane) = z;
        if (lane == 0) { g_c1[warp] = 0.f; g_c2[warp] = 0.f; }
    }
}

// ---------------- K5: fused GEMM with packed f32x2 FMA -------------------------
// x = agg@W1 + c1*(agg@W2) + c2*(agg@W3) + b
// A = g_agg [N,256], W = [768,64] as 3 panels of [256,64].
#define BM 64
#define KC 32
__global__ void __launch_bounds__(256) k_gemm(const float* __restrict__ W,
                                              const float* __restrict__ b) {
    __shared__ __align__(16) float  sA[KC * 68];   // [k][m], stride 68
    __shared__ float4 sW[3 * KC * 16];             // [p][k][j4]

    int t = threadIdx.x;
    int m0 = blockIdx.x * BM;
    int mi = t & 15;   // node quad
    int ji = t >> 4;   // col quad (0..15)

    // acc[p][mm][pair]: pair 0 = cols {4ji, 4ji+1}, pair 1 = {4ji+2, 4ji+3}
    unsigned long long acc[3][4][2];
    #pragma unroll
    for (int p = 0; p < 3; p++)
        #pragma unroll
        for (int a = 0; a < 4; a++) { acc[p][a][0] = 0ull; acc[p][a][1] = 0ull; }

    const float4* W4 = (const float4*)W;

    for (int kc = 0; kc < 256; kc += KC) {
        #pragma unroll
        for (int it = 0; it < 2; it++) {
            int idx = t + it * 256;
            int m = idx >> 3;
            int k4 = idx & 7;
            int gm = m0 + m;
            float4 v = make_float4(0.f, 0.f, 0.f, 0.f);
            if (gm < N_NODES)
                v = *(const float4*)(g_agg + (size_t)gm * 256 + kc + k4 * 4);
            sA[(k4 * 4 + 0) * 68 + m] = v.x;
            sA[(k4 * 4 + 1) * 68 + m] = v.y;
            sA[(k4 * 4 + 2) * 68 + m] = v.z;
            sA[(k4 * 4 + 3) * 68 + m] = v.w;
        }
        #pragma unroll
        for (int it = 0; it < 6; it++) {
            int idx = t + it * 256;
            int p = idx >> 9;
            int rem = idx & 511;
            int k = rem >> 4;
            int j4 = rem & 15;
            sW[idx] = W4[(p * 256 + kc + k) * 16 + j4];
        }
        __syncthreads();

        #pragma unroll 8
        for (int k = 0; k < KC; k++) {
            float4 a4 = *(const float4*)(sA + k * 68 + mi * 4);
            const float4* wp = sW + k * 16 + ji;
            ulonglong2 w0 = *(const ulonglong2*)(wp);
            ulonglong2 w1 = *(const ulonglong2*)(wp + 512);
            ulonglong2 w2 = *(const ulonglong2*)(wp + 1024);
            unsigned long long ap0 = pack2(a4.x);
            unsigned long long ap1 = pack2(a4.y);
            unsigned long long ap2 = pack2(a4.z);
            unsigned long long ap3 = pack2(a4.w);

            ffma2(acc[0][0][0], ap0, w0.x); ffma2(acc[0][0][1], ap0, w0.y);
            ffma2(acc[0][1][0], ap1, w0.x); ffma2(acc[0][1][1], ap1, w0.y);
            ffma2(acc[0][2][0], ap2, w0.x); ffma2(acc[0][2][1], ap2, w0.y);
            ffma2(acc[0][3][0], ap3, w0.x); ffma2(acc[0][3][1], ap3, w0.y);

            ffma2(acc[1][0][0], ap0, w1.x); ffma2(acc[1][0][1], ap0, w1.y);
            ffma2(acc[1][1][0], ap1, w1.x); ffma2(acc[1][1][1], ap1, w1.y);
            ffma2(acc[1][2][0], ap2, w1.x); ffma2(acc[1][2][1], ap2, w1.y);
            ffma2(acc[1][3][0], ap3, w1.x); ffma2(acc[1][3][1], ap3, w1.y);

            ffma2(acc[2][0][0], ap0, w2.x); ffma2(acc[2][0][1], ap0, w2.y);
            ffma2(acc[2][1][0], ap1, w2.x); ffma2(acc[2][1][1], ap1, w2.y);
            ffma2(acc[2][2][0], ap2, w2.x); ffma2(acc[2][2][1], ap2, w2.y);
            ffma2(acc[2][3][0], ap3, w2.x); ffma2(acc[2][3][1], ap3, w2.y);
        }
        __syncthreads();
    }

    float4 bb = ((const float4*)b)[ji];
    float bv[4] = {bb.x, bb.y, bb.z, bb.w};
    #pragma unroll
    for (int mm = 0; mm < 4; mm++) {
        int gm = m0 + mi * 4 + mm;
        if (gm >= N_NODES) continue;
        float c1 = g_c1[gm];
        float c2 = g_c2[gm];
        float4 r;
        r.x = lo32(acc[0][mm][0]) + c1 * lo32(acc[1][mm][0]) + c2 * lo32(acc[2][mm][0]) + bv[0];
        r.y = hi32(acc[0][mm][0]) + c1 * hi32(acc[1][mm][0]) + c2 * hi32(acc[2][mm][0]) + bv[1];
        r.z = lo32(acc[0][mm][1]) + c1 * lo32(acc[1][mm][1]) + c2 * lo32(acc[2][mm][1]) + bv[2];
        r.w = hi32(acc[0][mm][1]) + c1 * hi32(acc[1][mm][1]) + c2 * hi32(acc[2][mm][1]) + bv[3];
        *(float4*)(g_x + (size_t)gm * 64 + ji * 4) = r;
    }
}

// ---------------- K6: column sums / sumsq for BatchNorm ------------------------
__global__ void k_colred() {
    __shared__ float ssum[4][64];
    __shared__ float ssq[4][64];
    int t = threadIdx.x;
    int j = t & 63;
    int g = t >> 6;
    float s = 0.f, q = 0.f;
    for (int n = blockIdx.x * 4 + g; n < N_NODES; n += gridDim.x * 4) {
        float v = g_x[(size_t)n * 64 + j];
        s += v;
        q = fmaf(v, v, q);
    }
    ssum[g][j] = s;
    ssq[g][j] = q;
    __syncthreads();
    if (g == 0) {
        s = ssum[0][j] + ssum[1][j] + ssum[2][j] + ssum[3][j];
        q = ssq[0][j] + ssq[1][j] + ssq[2][j] + ssq[3][j];
        atomicAdd(&g_colsum[j], s);
        atomicAdd(&g_colsq[j], q);
    }
}

// ---------------- K7: BN + ReLU + residual -------------------------------------
__global__ void k_final(const float* __restrict__ h,
                        const float* __restrict__ gamma,
                        const float* __restrict__ beta,
                        float* __restrict__ out) {
    int i = blockIdx.x * blockDim.x + threadIdx.x;
    if (i >= N_NODES * F_DIM) return;
    int j = i & 63;
    const float invN = 1.0f / (float)N_NODES;
    float mu = g_colsum[j] * invN;
    float var = g_colsq[j] * invN - mu * mu;
    float inv = rsqrtf(var + EPS_BN);
    float v = gamma[j] * (g_x[i] - mu) * inv + beta[j];
    out[i] = h[i] + fmaxf(v, 0.f);
}

// ---------------- launch --------------------------------------------------------
extern "C" void kernel_launch(void* const* d_in, const int* in_sizes, int n_in,
                              void* d_out, int out_size) {
    const float* h     = (const float*)d_in[0];
    const int*   src   = (const int*)d_in[1];
    const int*   dst   = (const int*)d_in[2];
    const float* W     = (const float*)d_in[3];
    const float* b     = (const float*)d_in[4];
    const float* gamma = (const float*)d_in[5];
    const float* beta  = (const float*)d_in[6];
    float* out = (float*)d_out;

    k_zero<<<(N_NODES + 255) / 256, 256>>>();
    k_hist<<<(N_EDGES + 255) / 256, 256>>>(dst);
    k_part<<<NB, 256>>>();
    k_scan2<<<1, 256>>>();
    k_off<<<NB, 256>>>();
    k_scatter<<<(N_EDGES + 255) / 256, 256>>>(src, dst);
    k_agg<<<(N_NODES + 7) / 8, 256>>>(h);
    k_gemm<<<(N_NODES + BM - 1) / BM, 256>>>(W, b);
    k_colred<<<128, 256>>>();
    k_final<<<(N_NODES * F_DIM + 255) / 256, 256>>>(h, gamma, beta, out);
}

// round 4
// speedup vs baseline: 1.7481x; 1.3015x over previous
#include <cuda_runtime.h>
#include <cuda_bf16.h>
#include <math.h>
#include <stdint.h>

#define N_NODES 50000
#define N_EDGES 800000
#define F_DIM   64
#define AVG_D_LOG 2.833f
#define EPS_STD 1e-5f
#define EPS_BN  1e-5f
#define NB 196   // ceil(50000/256)

// ---------------- device scratch ---------------------------------------------
__device__ int   g_deg[N_NODES];
__device__ int   g_off[N_NODES];
__device__ int   g_cursor[N_NODES];
__device__ int   g_esrc[N_EDGES];
__device__ int   g_bsum[NB];
__device__ int   g_boff[NB];
__device__ float g_agg[(size_t)N_NODES * 256];   // [mean|max|min|std] per node
__device__ float g_c1[N_NODES];
__device__ float g_c2[N_NODES];
__device__ float g_x[(size_t)N_NODES * F_DIM];
__device__ float g_colsum[F_DIM];
__device__ float g_colsq[F_DIM];
__device__ __nv_bfloat16 g_whi[64 * 768];        // W^T hi split [n][k]
__device__ __nv_bfloat16 g_wlo[64 * 768];        // W^T lo split [n][k]

// ---------------- helpers -------------------------------------------------------
__device__ __forceinline__ uint32_t smem_u32(const void* p) {
    uint32_t r;
    asm("{ .reg .u64 t; cvta.to.shared.u64 t, %1; cvt.u32.u64 %0, t; }"
        : "=r"(r) : "l"(p));
    return r;
}
__device__ __forceinline__ void ldsm4(uint32_t& r0, uint32_t& r1,
                                      uint32_t& r2, uint32_t& r3, uint32_t a) {
    asm volatile("ldmatrix.sync.aligned.m8n8.x4.shared.b16 {%0,%1,%2,%3}, [%4];"
                 : "=r"(r0), "=r"(r1), "=r"(r2), "=r"(r3) : "r"(a));
}
__device__ __forceinline__ void mma_bf16(float* d,
                                         uint32_t a0, uint32_t a1, uint32_t a2, uint32_t a3,
                                         uint32_t b0, uint32_t b1) {
    asm volatile(
        "mma.sync.aligned.m16n8k16.row.col.f32.bf16.bf16.f32 "
        "{%0,%1,%2,%3}, {%4,%5,%6,%7}, {%8,%9}, {%0,%1,%2,%3};"
        : "+f"(d[0]), "+f"(d[1]), "+f"(d[2]), "+f"(d[3])
        : "r"(a0), "r"(a1), "r"(a2), "r"(a3), "r"(b0), "r"(b1));
}
__device__ __forceinline__ uint32_t packbf(float x, float y) {
    __nv_bfloat162 t;
    t.x = __float2bfloat16_rn(x);
    t.y = __float2bfloat16_rn(y);
    return *(uint32_t*)&t;
}
__device__ __forceinline__ float bferr(float x) {
    return x - __bfloat162float(__float2bfloat16_rn(x));
}

// ---------------- K0: zero ----------------------------------------------------
__global__ void k_zero() {
    int i = blockIdx.x * blockDim.x + threadIdx.x;
    if (i < N_NODES) g_deg[i] = 0;
    if (i < F_DIM) { g_colsum[i] = 0.f; g_colsq[i] = 0.f; }
}

// ---------------- K1: degree histogram ----------------------------------------
__global__ void k_hist(const int* __restrict__ dst) {
    int e = blockIdx.x * blockDim.x + threadIdx.x;
    if (e < N_EDGES) atomicAdd(&g_deg[dst[e]], 1);
}

// ---------------- Kw: split W[768,64] -> Wt hi/lo [64,768] bf16 ----------------
__global__ void k_wprep(const float* __restrict__ W) {
    int idx = blockIdx.x * blockDim.x + threadIdx.x;
    if (idx >= 768 * 64) return;
    int k = idx >> 6;
    int n = idx & 63;
    float w = W[idx];
    __nv_bfloat16 wh = __float2bfloat16_rn(w);
    __nv_bfloat16 wl = __float2bfloat16_rn(w - __bfloat162float(wh));
    g_whi[n * 768 + k] = wh;
    g_wlo[n * 768 + k] = wl;
}

// ---------------- K2a: per-block sums ------------------------------------------
__global__ void k_part() {
    __shared__ int s[256];
    int t = threadIdx.x;
    int i = blockIdx.x * 256 + t;
    int v = (i < N_NODES) ? g_deg[i] : 0;
    s[t] = v;
    __syncthreads();
    #pragma unroll
    for (int off = 128; off > 0; off >>= 1) {
        if (t < off) s[t] += s[t + off];
        __syncthreads();
    }
    if (t == 0) g_bsum[blockIdx.x] = s[0];
}

// ---------------- K2b: scan of block sums ---------------------------------------
__global__ void k_scan2() {
    __shared__ int s[256];
    int t = threadIdx.x;
    int v = (t < NB) ? g_bsum[t] : 0;
    s[t] = v;
    __syncthreads();
    #pragma unroll
    for (int off = 1; off < 256; off <<= 1) {
        int x = (t >= off) ? s[t - off] : 0;
        __syncthreads();
        s[t] += x;
        __syncthreads();
    }
    if (t < NB) g_boff[t] = s[t] - v;   // exclusive
}

// ---------------- K2c: local scan + global offset -------------------------------
__global__ void k_off() {
    __shared__ int s[256];
    int t = threadIdx.x;
    int i = blockIdx.x * 256 + t;
    int v = (i < N_NODES) ? g_deg[i] : 0;
    s[t] = v;
    __syncthreads();
    #pragma unroll
    for (int off = 1; off < 256; off <<= 1) {
        int x = (t >= off) ? s[t - off] : 0;
        __syncthreads();
        s[t] += x;
        __syncthreads();
    }
    if (i < N_NODES) {
        int ex = s[t] - v + g_boff[blockIdx.x];
        g_off[i] = ex;
        g_cursor[i] = ex;
    }
}

// ---------------- K3: scatter edges into CSR order ------------------------------
__global__ void k_scatter(const int* __restrict__ src, const int* __restrict__ dst) {
    int e = blockIdx.x * blockDim.x + threadIdx.x;
    if (e < N_EDGES) {
        int pos = atomicAdd(&g_cursor[dst[e]], 1);
        g_esrc[pos] = src[e];
    }
}

// ---------------- K4: warp-per-node aggregation ---------------------------------
__global__ void k_agg(const float* __restrict__ h) {
    int warp = (blockIdx.x * blockDim.x + threadIdx.x) >> 5;
    int lane = threadIdx.x & 31;
    if (warp >= N_NODES) return;

    int start = g_off[warp];
    int d = g_deg[warp];

    const float2* h2 = (const float2*)h;

    float s0 = 0.f, s1 = 0.f, q0 = 0.f, q1 = 0.f;
    float mx0 = -3.402823466e38f, mx1 = -3.402823466e38f;
    float mn0 =  3.402823466e38f, mn1 =  3.402823466e38f;

    int e = 0;
    for (; e + 2 <= d; e += 2) {
        int sa = g_esrc[start + e];
        int sb = g_esrc[start + e + 1];
        float2 va = h2[sa * 32 + lane];
        float2 vb = h2[sb * 32 + lane];
        s0 += va.x; s1 += va.y;
        q0 = fmaf(va.x, va.x, q0); q1 = fmaf(va.y, va.y, q1);
        mx0 = fmaxf(mx0, va.x); mx1 = fmaxf(mx1, va.y);
        mn0 = fminf(mn0, va.x); mn1 = fminf(mn1, va.y);
        s0 += vb.x; s1 += vb.y;
        q0 = fmaf(vb.x, vb.x, q0); q1 = fmaf(vb.y, vb.y, q1);
        mx0 = fmaxf(mx0, vb.x); mx1 = fmaxf(mx1, vb.y);
        mn0 = fminf(mn0, vb.x); mn1 = fminf(mn1, vb.y);
    }
    if (e < d) {
        int sa = g_esrc[start + e];
        float2 va = h2[sa * 32 + lane];
        s0 += va.x; s1 += va.y;
        q0 = fmaf(va.x, va.x, q0); q1 = fmaf(va.y, va.y, q1);
        mx0 = fmaxf(mx0, va.x); mx1 = fmaxf(mx1, va.y);
        mn0 = fminf(mn0, va.x); mn1 = fminf(mn1, va.y);
    }

    float* base = g_agg + (size_t)warp * 256;
    if (d > 0) {
        float inv = 1.0f / (float)d;
        float mean0 = s0 * inv, mean1 = s1 * inv;
        float var0 = fmaxf(q0 * inv - mean0 * mean0, 0.f);
        float var1 = fmaxf(q1 * inv - mean1 * mean1, 0.f);
        float std0 = sqrtf(var0 + EPS_STD);
        float std1 = sqrtf(var1 + EPS_STD);
        *(float2*)(base +       2 * lane) = make_float2(mean0, mean1);
        *(float2*)(base +  64 + 2 * lane) = make_float2(mx0, mx1);
        *(float2*)(base + 128 + 2 * lane) = make_float2(mn0, mn1);
        *(float2*)(base + 192 + 2 * lane) = make_float2(std0, std1);
        if (lane == 0) {
            float logD = logf((float)d + 1.0f);
            g_c1[warp] = logD / AVG_D_LOG;
            g_c2[warp] = AVG_D_LOG / fmaxf(logD, 1e-12f);
        }
    } else {
        float2 z = make_float2(0.f, 0.f);
        *(float2*)(base +       2 * lane) = z;
        *(float2*)(base +  64 + 2 * lane) = z;
        *(float2*)(base + 128 + 2 * lane) = z;
        *(float2*)(base + 192 + 2 * lane) = z;
        if (lane == 0) { g_c1[warp] = 0.f; g_c2[warp] = 0.f; }
    }
}

// ---------------- K5: mma.sync bf16-split GEMM ----------------------------------
// Per block: 128 rows x 64 cols x 3 panels, 8 warps (16-row strip each).
// D_p = Ah@Bh_p + Ah@Bl_p + Al@Bh_p, fp32 accum; epilogue D0 + c1*D1 + c2*D2 + b.
// SMEM: A hi/lo 128x64 bf16, rows padded to 144B; B 6 bufs (3 panels x hi/lo)
//       64x64 bf16, same padding. Stride 144B -> ldmatrix conflict-free.
#define AST 144                       // row stride bytes (72 bf16)
#define SA_HI 0
#define SA_LO (128 * AST)             // 18432
#define SB    (2 * 128 * AST)         // 36864
#define SBUF  (64 * AST)              // 9216
#define SMEM_MM (SB + 6 * SBUF)       // 92160

__global__ void __launch_bounds__(256)
k_gemm_mma(const float* __restrict__ bias) {
    extern __shared__ char smem[];
    const uint32_t sb = smem_u32(smem);
    int t = threadIdx.x;
    int w = t >> 5;
    int lane = t & 31;
    int m0 = blockIdx.x * 128;

    float acc[3][8][4];
    #pragma unroll
    for (int p = 0; p < 3; p++)
        #pragma unroll
        for (int nt = 0; nt < 8; nt++)
            #pragma unroll
            for (int j = 0; j < 4; j++) acc[p][nt][j] = 0.f;

    for (int c = 0; c < 4; c++) {
        __syncthreads();
        // ---- A chunk: 128 rows x 64 k, fp32 -> bf16 hi/lo ----
        #pragma unroll
        for (int it = 0; it < 4; it++) {
            int idx = t + it * 256;       // 0..1023
            int row = idx >> 3;
            int g = idx & 7;
            int gm = m0 + row;
            uint4 hi = make_uint4(0, 0, 0, 0);
            uint4 lo = make_uint4(0, 0, 0, 0);
            if (gm < N_NODES) {
                const float* srcp = g_agg + (size_t)gm * 256 + c * 64 + g * 8;
                float4 v0 = *(const float4*)srcp;
                float4 v1 = *(const float4*)(srcp + 4);
                hi.x = packbf(v0.x, v0.y); hi.y = packbf(v0.z, v0.w);
                hi.z = packbf(v1.x, v1.y); hi.w = packbf(v1.z, v1.w);
                lo.x = packbf(bferr(v0.x), bferr(v0.y));
                lo.y = packbf(bferr(v0.z), bferr(v0.w));
                lo.z = packbf(bferr(v1.x), bferr(v1.y));
                lo.w = packbf(bferr(v1.z), bferr(v1.w));
            }
            int off = row * AST + g * 16;
            *(uint4*)(smem + SA_HI + off) = hi;
            *(uint4*)(smem + SA_LO + off) = lo;
        }
        // ---- B chunk: 6 bufs (p0h,p0l,p1h,p1l,p2h,p2l), 64 n-rows x 64 k ----
        #pragma unroll
        for (int it = 0; it < 12; it++) {
            int idx = t + it * 256;       // 0..3071
            int buf = idx >> 9;
            int rem = idx & 511;
            int row = rem >> 3;
            int g = rem & 7;
            int p = buf >> 1;
            const __nv_bfloat16* srcp = ((buf & 1) ? g_wlo : g_whi)
                                        + row * 768 + p * 256 + c * 64 + g * 8;
            *(uint4*)(smem + SB + buf * SBUF + row * AST + g * 16) =
                *(const uint4*)srcp;
        }
        __syncthreads();

        #pragma unroll
        for (int ks = 0; ks < 4; ks++) {
            // A fragments (hi, lo) for this warp's 16-row strip
            int arow = w * 16 + (lane & 15);
            uint32_t aoff = (uint32_t)(arow * AST + ks * 32 + ((lane >> 4) << 4));
            uint32_t ah0, ah1, ah2, ah3, al0, al1, al2, al3;
            ldsm4(ah0, ah1, ah2, ah3, sb + SA_HI + aoff);
            ldsm4(al0, al1, al2, al3, sb + SA_LO + aoff);

            #pragma unroll
            for (int np = 0; np < 4; np++) {
                int nrow = np * 16 + (lane & 7) + ((lane & 16) ? 8 : 0);
                uint32_t boff = (uint32_t)(nrow * AST + ks * 32 + ((lane & 8) ? 16 : 0));
                #pragma unroll
                for (int p = 0; p < 3; p++) {
                    uint32_t bh0, bh1, bh2, bh3, bl0, bl1, bl2, bl3;
                    ldsm4(bh0, bh1, bh2, bh3, sb + SB + (2 * p)     * SBUF + boff);
                    ldsm4(bl0, bl1, bl2, bl3, sb + SB + (2 * p + 1) * SBUF + boff);
                    float* d0 = acc[p][np * 2];
                    float* d1 = acc[p][np * 2 + 1];
                    mma_bf16(d0, ah0, ah1, ah2, ah3, bh0, bh1);
                    mma_bf16(d0, ah0, ah1, ah2, ah3, bl0, bl1);
                    mma_bf16(d0, al0, al1, al2, al3, bh0, bh1);
                    mma_bf16(d1, ah0, ah1, ah2, ah3, bh2, bh3);
                    mma_bf16(d1, ah0, ah1, ah2, ah3, bl2, bl3);
                    mma_bf16(d1, al0, al1, al2, al3, bh2, bh3);
                }
            }
        }
    }

    // ---- epilogue: x = D0 + c1*D1 + c2*D2 + bias ----
    #pragma unroll
    for (int rr = 0; rr < 2; rr++) {
        int gm = m0 + w * 16 + (lane >> 2) + rr * 8;
        if (gm >= N_NODES) continue;
        float c1 = g_c1[gm];
        float c2 = g_c2[gm];
        float* dstp = g_x + (size_t)gm * 64;
        #pragma unroll
        for (int nt = 0; nt < 8; nt++) {
            int col = nt * 8 + (lane & 3) * 2;
            float b0 = bias[col];
            float b1 = bias[col + 1];
            int j0 = rr * 2;
            float v0 = acc[0][nt][j0]     + c1 * acc[1][nt][j0]     + c2 * acc[2][nt][j0]     + b0;
            float v1 = acc[0][nt][j0 + 1] + c1 * acc[1][nt][j0 + 1] + c2 * acc[2][nt][j0 + 1] + b1;
            *(float2*)(dstp + col) = make_float2(v0, v1);
        }
    }
}

// ---------------- K6: column sums / sumsq for BatchNorm -------------------------
__global__ void k_colred() {
    __shared__ float ssum[4][64];
    __shared__ float ssq[4][64];
    int t = threadIdx.x;
    int j = t & 63;
    int g = t >> 6;
    float s = 0.f, q = 0.f;
    for (int n = blockIdx.x * 4 + g; n < N_NODES; n += gridDim.x * 4) {
        float v = g_x[(size_t)n * 64 + j];
        s += v;
        q = fmaf(v, v, q);
    }
    ssum[g][j] = s;
    ssq[g][j] = q;
    __syncthreads();
    if (g == 0) {
        s = ssum[0][j] + ssum[1][j] + ssum[2][j] + ssum[3][j];
        q = ssq[0][j] + ssq[1][j] + ssq[2][j] + ssq[3][j];
        atomicAdd(&g_colsum[j], s);
        atomicAdd(&g_colsq[j], q);
    }
}

// ---------------- K7: BN + ReLU + residual --------------------------------------
__global__ void k_final(const float* __restrict__ h,
                        const float* __restrict__ gamma,
                        const float* __restrict__ beta,
                        float* __restrict__ out) {
    int i = blockIdx.x * blockDim.x + threadIdx.x;
    if (i >= N_NODES * F_DIM) return;
    int j = i & 63;
    const float invN = 1.0f / (float)N_NODES;
    float mu = g_colsum[j] * invN;
    float var = g_colsq[j] * invN - mu * mu;
    float inv = rsqrtf(var + EPS_BN);
    float v = gamma[j] * (g_x[i] - mu) * inv + beta[j];
    out[i] = h[i] + fmaxf(v, 0.f);
}

// ---------------- launch ----------------------------------------------------------
extern "C" void kernel_launch(void* const* d_in, const int* in_sizes, int n_in,
                              void* d_out, int out_size) {
    const float* h     = (const float*)d_in[0];
    const int*   src   = (const int*)d_in[1];
    const int*   dst   = (const int*)d_in[2];
    const float* W     = (const float*)d_in[3];
    const float* b     = (const float*)d_in[4];
    const float* gamma = (const float*)d_in[5];
    const float* beta  = (const float*)d_in[6];
    float* out = (float*)d_out;

    cudaFuncSetAttribute(k_gemm_mma, cudaFuncAttributeMaxDynamicSharedMemorySize, SMEM_MM);

    k_zero<<<(N_NODES + 255) / 256, 256>>>();
    k_hist<<<(N_EDGES + 255) / 256, 256>>>(dst);
    k_wprep<<<192, 256>>>(W);
    k_part<<<NB, 256>>>();
    k_scan2<<<1, 256>>>();
    k_off<<<NB, 256>>>();
    k_scatter<<<(N_EDGES + 255) / 256, 256>>>(src, dst);
    k_agg<<<(N_NODES + 7) / 8, 256>>>(h);
    k_gemm_mma<<<(N_NODES + 127) / 128, 256, SMEM_MM>>>(b);
    k_colred<<<128, 256>>>();
    k_final<<<(N_NODES * F_DIM + 255) / 256, 256>>>(h, gamma, beta, out);
}

// round 5
// speedup vs baseline: 2.1258x; 1.2161x over previous
#include <cuda_runtime.h>
#include <cuda_bf16.h>
#include <math.h>
#include <stdint.h>

#define N_NODES 50000
#define N_EDGES 800000
#define F_DIM   64
#define AVG_D_LOG 2.833f
#define EPS_STD 1e-5f
#define EPS_BN  1e-5f
#define NB 196   // ceil(50000/256)
#define A_FLAG 0x40000000u
#define P_FLAG 0x80000000u

// ---------------- device scratch (all zero-initialized at load) ----------------
__device__ int   g_deg[N_NODES];       // zeroed by k_agg after use
__device__ int   g_off[N_NODES];
__device__ int   g_cursor[N_NODES];
__device__ int   g_esrc[N_EDGES];
__device__ unsigned g_pkt[NB];         // scan lookback state; zeroed by k_agg
__device__ float g_agg[(size_t)N_NODES * 256];
__device__ float g_c1[N_NODES];
__device__ float g_c2[N_NODES];
__device__ float g_x[(size_t)N_NODES * F_DIM];
__device__ float g_colsum[F_DIM];      // zeroed by k_agg, filled by gemm epilogue
__device__ float g_colsq[F_DIM];
__device__ __nv_bfloat16 g_whi[64 * 768];
__device__ __nv_bfloat16 g_wlo[64 * 768];

// ---------------- helpers -------------------------------------------------------
__device__ __forceinline__ uint32_t smem_u32(const void* p) {
    uint32_t r;
    asm("{ .reg .u64 t; cvta.to.shared.u64 t, %1; cvt.u32.u64 %0, t; }"
        : "=r"(r) : "l"(p));
    return r;
}
__device__ __forceinline__ void ldsm4(uint32_t& r0, uint32_t& r1,
                                      uint32_t& r2, uint32_t& r3, uint32_t a) {
    asm volatile("ldmatrix.sync.aligned.m8n8.x4.shared.b16 {%0,%1,%2,%3}, [%4];"
                 : "=r"(r0), "=r"(r1), "=r"(r2), "=r"(r3) : "r"(a));
}
__device__ __forceinline__ void mma_bf16(float* d,
                                         uint32_t a0, uint32_t a1, uint32_t a2, uint32_t a3,
                                         uint32_t b0, uint32_t b1) {
    asm volatile(
        "mma.sync.aligned.m16n8k16.row.col.f32.bf16.bf16.f32 "
        "{%0,%1,%2,%3}, {%4,%5,%6,%7}, {%8,%9}, {%0,%1,%2,%3};"
        : "+f"(d[0]), "+f"(d[1]), "+f"(d[2]), "+f"(d[3])
        : "r"(a0), "r"(a1), "r"(a2), "r"(a3), "r"(b0), "r"(b1));
}
__device__ __forceinline__ uint32_t packbf(float x, float y) {
    __nv_bfloat162 t;
    t.x = __float2bfloat16_rn(x);
    t.y = __float2bfloat16_rn(y);
    return *(uint32_t*)&t;
}
__device__ __forceinline__ float bferr(float x) {
    return x - __bfloat162float(__float2bfloat16_rn(x));
}

// ---------------- K1: degree histogram + W split (fused) ------------------------
__global__ void k_hist_wprep(const int* __restrict__ dst, const float* __restrict__ W) {
    int e = blockIdx.x * blockDim.x + threadIdx.x;
    if (e < N_EDGES) atomicAdd(&g_deg[dst[e]], 1);
    if (e < 768 * 64) {
        int k = e >> 6;
        int n = e & 63;
        float w = W[e];
        __nv_bfloat16 wh = __float2bfloat16_rn(w);
        __nv_bfloat16 wl = __float2bfloat16_rn(w - __bfloat162float(wh));
        g_whi[n * 768 + k] = wh;
        g_wlo[n * 768 + k] = wl;
    }
}

// ---------------- K2: single-pass decoupled-lookback scan -----------------------
// 196 blocks x 256 threads; all co-resident -> no deadlock.
__global__ void k_scan(void) {
    __shared__ int s[256];
    __shared__ unsigned sprefix;
    int t = threadIdx.x;
    int bidx = blockIdx.x;
    int i = bidx * 256 + t;
    int v = (i < N_NODES) ? g_deg[i] : 0;
    s[t] = v;
    __syncthreads();
    #pragma unroll
    for (int off = 1; off < 256; off <<= 1) {
        int x = (t >= off) ? s[t - off] : 0;
        __syncthreads();
        s[t] += x;
        __syncthreads();
    }
    int total = s[255];

    if (t == 0) {
        unsigned pub = (bidx == 0) ? (P_FLAG | (unsigned)total)
                                   : (A_FLAG | (unsigned)total);
        atomicExch(&g_pkt[bidx], pub);
        if (bidx == 0) sprefix = 0;
    }

    if (bidx > 0 && t < 32) {
        unsigned running = 0;
        int idx = bidx - 1;
        for (;;) {
            int j = idx - t;
            unsigned p;
            if (j >= 0) {
                do { p = ((volatile unsigned*)g_pkt)[j]; } while (p == 0);
            } else {
                p = P_FLAG;   // fake prefix-0 beyond tile 0; never selected (tile 0 is real P)
            }
            unsigned pm = __ballot_sync(0xffffffffu, (p & P_FLAG) != 0);
            unsigned val = p & 0x3fffffffu;
            if (pm) {
                int k = __ffs(pm) - 1;         // nearest prefix
                unsigned contrib = (t <= k) ? val : 0;
                #pragma unroll
                for (int o = 16; o > 0; o >>= 1)
                    contrib += __shfl_down_sync(0xffffffffu, contrib, o);
                if (t == 0) sprefix = running + contrib;
                break;
            } else {
                unsigned contrib = (j >= 0) ? val : 0;
                #pragma unroll
                for (int o = 16; o > 0; o >>= 1)
                    contrib += __shfl_down_sync(0xffffffffu, contrib, o);
                running += __shfl_sync(0xffffffffu, contrib, 0);
                idx -= 32;
            }
        }
        if (t == 0)
            atomicExch(&g_pkt[bidx], P_FLAG | (sprefix + (unsigned)total));
    }
    __syncthreads();

    if (i < N_NODES) {
        int ex = (int)sprefix + s[t] - v;
        g_off[i] = ex;
        g_cursor[i] = ex;
    }
}

// ---------------- K3: scatter edges into CSR order ------------------------------
__global__ void k_scatter(const int* __restrict__ src, const int* __restrict__ dst) {
    int e = blockIdx.x * blockDim.x + threadIdx.x;
    if (e < N_EDGES) {
        int pos = atomicAdd(&g_cursor[dst[e]], 1);
        g_esrc[pos] = src[e];
    }
}

// ---------------- K4: warp-per-node aggregation (+ next-call zeroing) ------------
__global__ void k_agg(const float* __restrict__ h) {
    // block 0 resets the cross-call accumulators for the NEXT invocation
    if (blockIdx.x == 0) {
        int tt = threadIdx.x;
        if (tt < F_DIM) { g_colsum[tt] = 0.f; g_colsq[tt] = 0.f; }
        if (tt < NB) g_pkt[tt] = 0u;
    }

    int warp = (blockIdx.x * blockDim.x + threadIdx.x) >> 5;
    int lane = threadIdx.x & 31;
    if (warp >= N_NODES) return;

    int start = g_off[warp];
    int d = g_deg[warp];

    const float2* h2 = (const float2*)h;

    float s0 = 0.f, s1 = 0.f, q0 = 0.f, q1 = 0.f;
    float mx0 = -3.402823466e38f, mx1 = -3.402823466e38f;
    float mn0 =  3.402823466e38f, mn1 =  3.402823466e38f;

    int e = 0;
    for (; e + 4 <= d; e += 4) {
        int sa = g_esrc[start + e];
        int sb = g_esrc[start + e + 1];
        int sc = g_esrc[start + e + 2];
        int sd = g_esrc[start + e + 3];
        float2 va = h2[sa * 32 + lane];
        float2 vb = h2[sb * 32 + lane];
        float2 vc = h2[sc * 32 + lane];
        float2 vd = h2[sd * 32 + lane];
        s0 += va.x; s1 += va.y;
        q0 = fmaf(va.x, va.x, q0); q1 = fmaf(va.y, va.y, q1);
        mx0 = fmaxf(mx0, va.x); mx1 = fmaxf(mx1, va.y);
        mn0 = fminf(mn0, va.x); mn1 = fminf(mn1, va.y);
        s0 += vb.x; s1 += vb.y;
        q0 = fmaf(vb.x, vb.x, q0); q1 = fmaf(vb.y, vb.y, q1);
        mx0 = fmaxf(mx0, vb.x); mx1 = fmaxf(mx1, vb.y);
        mn0 = fminf(mn0, vb.x); mn1 = fminf(mn1, vb.y);
        s0 += vc.x; s1 += vc.y;
        q0 = fmaf(vc.x, vc.x, q0); q1 = fmaf(vc.y, vc.y, q1);
        mx0 = fmaxf(mx0, vc.x); mx1 = fmaxf(mx1, vc.y);
        mn0 = fminf(mn0, vc.x); mn1 = fminf(mn1, vc.y);
        s0 += vd.x; s1 += vd.y;
        q0 = fmaf(vd.x, vd.x, q0); q1 = fmaf(vd.y, vd.y, q1);
        mx0 = fmaxf(mx0, vd.x); mx1 = fmaxf(mx1, vd.y);
        mn0 = fminf(mn0, vd.x); mn1 = fminf(mn1, vd.y);
    }
    for (; e < d; e++) {
        int sa = g_esrc[start + e];
        float2 va = h2[sa * 32 + lane];
        s0 += va.x; s1 += va.y;
        q0 = fmaf(va.x, va.x, q0); q1 = fmaf(va.y, va.y, q1);
        mx0 = fmaxf(mx0, va.x); mx1 = fmaxf(mx1, va.y);
        mn0 = fminf(mn0, va.x); mn1 = fminf(mn1, va.y);
    }

    float* base = g_agg + (size_t)warp * 256;
    if (d > 0) {
        float inv = 1.0f / (float)d;
        float mean0 = s0 * inv, mean1 = s1 * inv;
        float var0 = fmaxf(q0 * inv - mean0 * mean0, 0.f);
        float var1 = fmaxf(q1 * inv - mean1 * mean1, 0.f);
        float std0 = sqrtf(var0 + EPS_STD);
        float std1 = sqrtf(var1 + EPS_STD);
        *(float2*)(base +       2 * lane) = make_float2(mean0, mean1);
        *(float2*)(base +  64 + 2 * lane) = make_float2(mx0, mx1);
        *(float2*)(base + 128 + 2 * lane) = make_float2(mn0, mn1);
        *(float2*)(base + 192 + 2 * lane) = make_float2(std0, std1);
        if (lane == 0) {
            float logD = logf((float)d + 1.0f);
            g_c1[warp] = logD / AVG_D_LOG;
            g_c2[warp] = AVG_D_LOG / fmaxf(logD, 1e-12f);
        }
    } else {
        float2 z = make_float2(0.f, 0.f);
        *(float2*)(base +       2 * lane) = z;
        *(float2*)(base +  64 + 2 * lane) = z;
        *(float2*)(base + 128 + 2 * lane) = z;
        *(float2*)(base + 192 + 2 * lane) = z;
        if (lane == 0) { g_c1[warp] = 0.f; g_c2[warp] = 0.f; }
    }
    if (lane == 0) g_deg[warp] = 0;   // reset for next call
}

// ---------------- K5: mma.sync bf16-split GEMM + fused BN column stats -----------
#define AST 144
#define SA_HI 0
#define SA_LO (128 * AST)
#define SB    (2 * 128 * AST)
#define SBUF  (64 * AST)
#define SMEM_MM (SB + 6 * SBUF)

__global__ void __launch_bounds__(256)
k_gemm_mma(const float* __restrict__ bias) {
    extern __shared__ char smem[];
    const uint32_t sb = smem_u32(smem);
    int t = threadIdx.x;
    int w = t >> 5;
    int lane = t & 31;
    int m0 = blockIdx.x * 128;

    float acc[3][8][4];
    #pragma unroll
    for (int p = 0; p < 3; p++)
        #pragma unroll
        for (int nt = 0; nt < 8; nt++)
            #pragma unroll
            for (int j = 0; j < 4; j++) acc[p][nt][j] = 0.f;

    for (int c = 0; c < 4; c++) {
        __syncthreads();
        #pragma unroll
        for (int it = 0; it < 4; it++) {
            int idx = t + it * 256;
            int row = idx >> 3;
            int g = idx & 7;
            int gm = m0 + row;
            uint4 hi = make_uint4(0, 0, 0, 0);
            uint4 lo = make_uint4(0, 0, 0, 0);
            if (gm < N_NODES) {
                const float* srcp = g_agg + (size_t)gm * 256 + c * 64 + g * 8;
                float4 v0 = *(const float4*)srcp;
                float4 v1 = *(const float4*)(srcp + 4);
                hi.x = packbf(v0.x, v0.y); hi.y = packbf(v0.z, v0.w);
                hi.z = packbf(v1.x, v1.y); hi.w = packbf(v1.z, v1.w);
                lo.x = packbf(bferr(v0.x), bferr(v0.y));
                lo.y = packbf(bferr(v0.z), bferr(v0.w));
                lo.z = packbf(bferr(v1.x), bferr(v1.y));
                lo.w = packbf(bferr(v1.z), bferr(v1.w));
            }
            int off = row * AST + g * 16;
            *(uint4*)(smem + SA_HI + off) = hi;
            *(uint4*)(smem + SA_LO + off) = lo;
        }
        #pragma unroll
        for (int it = 0; it < 12; it++) {
            int idx = t + it * 256;
            int buf = idx >> 9;
            int rem = idx & 511;
            int row = rem >> 3;
            int g = rem & 7;
            int p = buf >> 1;
            const __nv_bfloat16* srcp = ((buf & 1) ? g_wlo : g_whi)
                                        + row * 768 + p * 256 + c * 64 + g * 8;
            *(uint4*)(smem + SB + buf * SBUF + row * AST + g * 16) =
                *(const uint4*)srcp;
        }
        __syncthreads();

        #pragma unroll
        for (int ks = 0; ks < 4; ks++) {
            int arow = w * 16 + (lane & 15);
            uint32_t aoff = (uint32_t)(arow * AST + ks * 32 + ((lane >> 4) << 4));
            uint32_t ah0, ah1, ah2, ah3, al0, al1, al2, al3;
            ldsm4(ah0, ah1, ah2, ah3, sb + SA_HI + aoff);
            ldsm4(al0, al1, al2, al3, sb + SA_LO + aoff);

            #pragma unroll
            for (int np = 0; np < 4; np++) {
                int nrow = np * 16 + (lane & 7) + ((lane & 16) ? 8 : 0);
                uint32_t boff = (uint32_t)(nrow * AST + ks * 32 + ((lane & 8) ? 16 : 0));
                #pragma unroll
                for (int p = 0; p < 3; p++) {
                    uint32_t bh0, bh1, bh2, bh3, bl0, bl1, bl2, bl3;
                    ldsm4(bh0, bh1, bh2, bh3, sb + SB + (2 * p)     * SBUF + boff);
                    ldsm4(bl0, bl1, bl2, bl3, sb + SB + (2 * p + 1) * SBUF + boff);
                    float* d0 = acc[p][np * 2];
                    float* d1 = acc[p][np * 2 + 1];
                    mma_bf16(d0, ah0, ah1, ah2, ah3, bh0, bh1);
                    mma_bf16(d0, ah0, ah1, ah2, ah3, bl0, bl1);
                    mma_bf16(d0, al0, al1, al2, al3, bh0, bh1);
                    mma_bf16(d1, ah0, ah1, ah2, ah3, bh2, bh3);
                    mma_bf16(d1, ah0, ah1, ah2, ah3, bl2, bl3);
                    mma_bf16(d1, al0, al1, al2, al3, bh2, bh3);
                }
            }
        }
    }

    // ---- epilogue: x = D0 + c1*D1 + c2*D2 + bias; fused BN column stats ----
    __syncthreads();                       // smem reuse for stats
    float* swsum = (float*)smem;           // [8][64]
    float* swsq  = (float*)(smem + 2048);  // [8][64]

    int rowA = m0 + w * 16 + (lane >> 2);
    int rowB = rowA + 8;
    bool va = rowA < N_NODES, vb = rowB < N_NODES;
    float c1a = 0.f, c2a = 0.f, c1b = 0.f, c2b = 0.f;
    if (va) { c1a = g_c1[rowA]; c2a = g_c2[rowA]; }
    if (vb) { c1b = g_c1[rowB]; c2b = g_c2[rowB]; }

    #pragma unroll
    for (int nt = 0; nt < 8; nt++) {
        int col = nt * 8 + (lane & 3) * 2;
        float b0 = bias[col];
        float b1 = bias[col + 1];
        float x0a = acc[0][nt][0] + c1a * acc[1][nt][0] + c2a * acc[2][nt][0] + b0;
        float x1a = acc[0][nt][1] + c1a * acc[1][nt][1] + c2a * acc[2][nt][1] + b1;
        float x0b = acc[0][nt][2] + c1b * acc[1][nt][2] + c2b * acc[2][nt][2] + b0;
        float x1b = acc[0][nt][3] + c1b * acc[1][nt][3] + c2b * acc[2][nt][3] + b1;
        if (va) *(float2*)(g_x + (size_t)rowA * 64 + col) = make_float2(x0a, x1a);
        if (vb) *(float2*)(g_x + (size_t)rowB * 64 + col) = make_float2(x0b, x1b);

        float s0 = (va ? x0a : 0.f) + (vb ? x0b : 0.f);
        float s1 = (va ? x1a : 0.f) + (vb ? x1b : 0.f);
        float q0 = (va ? x0a * x0a : 0.f) + (vb ? x0b * x0b : 0.f);
        float q1 = (va ? x1a * x1a : 0.f) + (vb ? x1b * x1b : 0.f);
        #pragma unroll
        for (int o = 4; o <= 16; o <<= 1) {
            s0 += __shfl_xor_sync(0xffffffffu, s0, o);
            s1 += __shfl_xor_sync(0xffffffffu, s1, o);
            q0 += __shfl_xor_sync(0xffffffffu, q0, o);
            q1 += __shfl_xor_sync(0xffffffffu, q1, o);
        }
        if (lane < 4) {
            swsum[w * 64 + nt * 8 + lane * 2]     = s0;
            swsum[w * 64 + nt * 8 + lane * 2 + 1] = s1;
            swsq [w * 64 + nt * 8 + lane * 2]     = q0;
            swsq [w * 64 + nt * 8 + lane * 2 + 1] = q1;
        }
    }
    __syncthreads();
    if (t < 64) {
        float s = 0.f, q = 0.f;
        #pragma unroll
        for (int k = 0; k < 8; k++) {
            s += swsum[k * 64 + t];
            q += swsq[k * 64 + t];
        }
        atomicAdd(&g_colsum[t], s);
        atomicAdd(&g_colsq[t], q);
    }
}

// ---------------- K6: BN + ReLU + residual ---------------------------------------
__global__ void k_final(const float* __restrict__ h,
                        const float* __restrict__ gamma,
                        const float* __restrict__ beta,
                        float* __restrict__ out) {
    int i = blockIdx.x * blockDim.x + threadIdx.x;
    if (i >= N_NODES * F_DIM) return;
    int j = i & 63;
    const float invN = 1.0f / (float)N_NODES;
    float mu = g_colsum[j] * invN;
    float var = g_colsq[j] * invN - mu * mu;
    float inv = rsqrtf(var + EPS_BN);
    float v = gamma[j] * (g_x[i] - mu) * inv + beta[j];
    out[i] = h[i] + fmaxf(v, 0.f);
}

// ---------------- launch -----------------------------------------------------------
extern "C" void kernel_launch(void* const* d_in, const int* in_sizes, int n_in,
                              void* d_out, int out_size) {
    const float* h     = (const float*)d_in[0];
    const int*   src   = (const int*)d_in[1];
    const int*   dst   = (const int*)d_in[2];
    const float* W     = (const float*)d_in[3];
    const float* b     = (const float*)d_in[4];
    const float* gamma = (const float*)d_in[5];
    const float* beta  = (const float*)d_in[6];
    float* out = (float*)d_out;

    cudaFuncSetAttribute(k_gemm_mma, cudaFuncAttributeMaxDynamicSharedMemorySize, SMEM_MM);

    k_hist_wprep<<<(N_EDGES + 255) / 256, 256>>>(dst, W);
    k_scan<<<NB, 256>>>();
    k_scatter<<<(N_EDGES + 255) / 256, 256>>>(src, dst);
    k_agg<<<(N_NODES + 7) / 8, 256>>>(h);
    k_gemm_mma<<<(N_NODES + 127) / 128, 256, SMEM_MM>>>(b);
    k_final<<<(N_NODES * F_DIM + 255) / 256, 256>>>(h, gamma, beta, out);
}

// round 6
// speedup vs baseline: 2.2316x; 1.0498x over previous
#include <cuda_runtime.h>
#include <cuda_bf16.h>
#include <math.h>
#include <stdint.h>

#define N_NODES 50000
#define N_EDGES 800000
#define F_DIM   64
#define AVG_D_LOG 2.833f
#define EPS_STD 1e-5f
#define EPS_BN  1e-5f
#define NB 196   // ceil(50000/256)
#define A_FLAG 0x40000000u
#define P_FLAG 0x80000000u

typedef unsigned long long ull;

// ---------------- device scratch (all zero-initialized at load) ----------------
__device__ int   g_deg[N_NODES];       // zeroed by k_agg after use
__device__ int   g_off[N_NODES];
__device__ int   g_cursor[N_NODES];
__device__ int   g_esrc[N_EDGES];
__device__ unsigned g_pkt[NB];         // scan lookback state; zeroed by k_agg
__device__ float g_agg[(size_t)N_NODES * 256];
__device__ float g_c1[N_NODES];
__device__ float g_c2[N_NODES];
__device__ float g_x[(size_t)N_NODES * F_DIM];
__device__ float g_colsum[F_DIM];
__device__ float g_colsq[F_DIM];
__device__ __nv_bfloat16 g_whi[64 * 768];
__device__ __nv_bfloat16 g_wlo[64 * 768];

// ---------------- helpers -------------------------------------------------------
__device__ __forceinline__ uint32_t smem_u32(const void* p) {
    uint32_t r;
    asm("{ .reg .u64 t; cvta.to.shared.u64 t, %1; cvt.u32.u64 %0, t; }"
        : "=r"(r) : "l"(p));
    return r;
}
__device__ __forceinline__ void ldsm4(uint32_t& r0, uint32_t& r1,
                                      uint32_t& r2, uint32_t& r3, uint32_t a) {
    asm volatile("ldmatrix.sync.aligned.m8n8.x4.shared.b16 {%0,%1,%2,%3}, [%4];"
                 : "=r"(r0), "=r"(r1), "=r"(r2), "=r"(r3) : "r"(a));
}
__device__ __forceinline__ void mma_bf16(float* d,
                                         uint32_t a0, uint32_t a1, uint32_t a2, uint32_t a3,
                                         uint32_t b0, uint32_t b1) {
    asm volatile(
        "mma.sync.aligned.m16n8k16.row.col.f32.bf16.bf16.f32 "
        "{%0,%1,%2,%3}, {%4,%5,%6,%7}, {%8,%9}, {%0,%1,%2,%3};"
        : "+f"(d[0]), "+f"(d[1]), "+f"(d[2]), "+f"(d[3])
        : "r"(a0), "r"(a1), "r"(a2), "r"(a3), "r"(b0), "r"(b1));
}
__device__ __forceinline__ uint32_t packbf(float x, float y) {
    __nv_bfloat162 t;
    t.x = __float2bfloat16_rn(x);
    t.y = __float2bfloat16_rn(y);
    return *(uint32_t*)&t;
}
__device__ __forceinline__ float bferr(float x) {
    return x - __bfloat162float(__float2bfloat16_rn(x));
}
// packed f32x2 (plain sm_100+ PTX; compiled fine under compute_103 in R2)
__device__ __forceinline__ void add2(ull& d, ull a) {
    asm("add.rn.f32x2 %0, %0, %1;" : "+l"(d) : "l"(a));
}
__device__ __forceinline__ void fma2(ull& d, ull a) {
    asm("fma.rn.f32x2 %0, %1, %1, %0;" : "+l"(d) : "l"(a));
}
__device__ __forceinline__ float lo32(ull v) { return __uint_as_float((unsigned)v); }
__device__ __forceinline__ float hi32(ull v) { return __uint_as_float((unsigned)(v >> 32)); }
__device__ __forceinline__ ull mk2(float lo, float hi) {
    ull r;
    asm("mov.b64 %0, {%1, %2};" : "=l"(r) : "f"(lo), "f"(hi));
    return r;
}

// ---------------- K1: degree histogram (x4) + W split (fused) --------------------
__global__ void k_hist_wprep(const int* __restrict__ dst, const float* __restrict__ W) {
    int t = blockIdx.x * blockDim.x + threadIdx.x;
    if (t < N_EDGES / 4) {
        int4 d4 = ((const int4*)dst)[t];
        atomicAdd(&g_deg[d4.x], 1);
        atomicAdd(&g_deg[d4.y], 1);
        atomicAdd(&g_deg[d4.z], 1);
        atomicAdd(&g_deg[d4.w], 1);
    }
    if (t < 768 * 64) {
        int k = t >> 6;
        int n = t & 63;
        float w = W[t];
        __nv_bfloat16 wh = __float2bfloat16_rn(w);
        __nv_bfloat16 wl = __float2bfloat16_rn(w - __bfloat162float(wh));
        g_whi[n * 768 + k] = wh;
        g_wlo[n * 768 + k] = wl;
    }
}

// ---------------- K2: single-pass decoupled-lookback scan ------------------------
__global__ void k_scan(void) {
    __shared__ int s[256];
    __shared__ unsigned sprefix;
    int t = threadIdx.x;
    int bidx = blockIdx.x;
    int i = bidx * 256 + t;
    int v = (i < N_NODES) ? g_deg[i] : 0;
    s[t] = v;
    __syncthreads();
    #pragma unroll
    for (int off = 1; off < 256; off <<= 1) {
        int x = (t >= off) ? s[t - off] : 0;
        __syncthreads();
        s[t] += x;
        __syncthreads();
    }
    int total = s[255];

    if (t == 0) {
        unsigned pub = (bidx == 0) ? (P_FLAG | (unsigned)total)
                                   : (A_FLAG | (unsigned)total);
        atomicExch(&g_pkt[bidx], pub);
        if (bidx == 0) sprefix = 0;
    }

    if (bidx > 0 && t < 32) {
        unsigned running = 0;
        int idx = bidx - 1;
        for (;;) {
            int j = idx - t;
            unsigned p;
            if (j >= 0) {
                do { p = ((volatile unsigned*)g_pkt)[j]; } while (p == 0);
            } else {
                p = P_FLAG;
            }
            unsigned pm = __ballot_sync(0xffffffffu, (p & P_FLAG) != 0);
            unsigned val = p & 0x3fffffffu;
            if (pm) {
                int k = __ffs(pm) - 1;
                unsigned contrib = (t <= k) ? val : 0;
                #pragma unroll
                for (int o = 16; o > 0; o >>= 1)
                    contrib += __shfl_down_sync(0xffffffffu, contrib, o);
                if (t == 0) sprefix = running + contrib;
                break;
            } else {
                unsigned contrib = (j >= 0) ? val : 0;
                #pragma unroll
                for (int o = 16; o > 0; o >>= 1)
                    contrib += __shfl_down_sync(0xffffffffu, contrib, o);
                running += __shfl_sync(0xffffffffu, contrib, 0);
                idx -= 32;
            }
        }
        if (t == 0)
            atomicExch(&g_pkt[bidx], P_FLAG | (sprefix + (unsigned)total));
    }
    __syncthreads();

    if (i < N_NODES) {
        int ex = (int)sprefix + s[t] - v;
        g_off[i] = ex;
        g_cursor[i] = ex;
    }
}

// ---------------- K3: scatter edges, 4 per thread (MLP=4) ------------------------
__global__ void k_scatter(const int* __restrict__ src, const int* __restrict__ dst) {
    int t = blockIdx.x * blockDim.x + threadIdx.x;
    if (t >= N_EDGES / 4) return;
    int4 d4 = ((const int4*)dst)[t];
    int4 s4 = ((const int4*)src)[t];
    int p0 = atomicAdd(&g_cursor[d4.x], 1);
    int p1 = atomicAdd(&g_cursor[d4.y], 1);
    int p2 = atomicAdd(&g_cursor[d4.z], 1);
    int p3 = atomicAdd(&g_cursor[d4.w], 1);
    g_esrc[p0] = s4.x;
    g_esrc[p1] = s4.y;
    g_esrc[p2] = s4.z;
    g_esrc[p3] = s4.w;
}

// ---------------- K4: warp-per-node aggregation, packed f32x2 --------------------
__global__ void k_agg(const float* __restrict__ h) {
    if (blockIdx.x == 0) {
        int tt = threadIdx.x;
        if (tt < F_DIM) { g_colsum[tt] = 0.f; g_colsq[tt] = 0.f; }
        if (tt < NB) g_pkt[tt] = 0u;
    }

    int warp = (blockIdx.x * blockDim.x + threadIdx.x) >> 5;
    int lane = threadIdx.x & 31;
    if (warp >= N_NODES) return;

    int start = g_off[warp];
    int d = g_deg[warp];

    const ull* hl = (const ull*)h + lane;   // lane owns features 2*lane, 2*lane+1

    ull sum = 0ull;                         // (0.0f, 0.0f)
    ull sq  = 0ull;
    float mx0 = -3.402823466e38f, mx1 = -3.402823466e38f;
    float mn0 =  3.402823466e38f, mn1 =  3.402823466e38f;

    int e = 0;
    for (; e + 4 <= d; e += 4) {
        int sa = g_esrc[start + e];
        int sb = g_esrc[start + e + 1];
        int sc = g_esrc[start + e + 2];
        int sd = g_esrc[start + e + 3];
        ull va = hl[sa * 32];
        ull vb = hl[sb * 32];
        ull vc = hl[sc * 32];
        ull vd = hl[sd * 32];
        add2(sum, va); fma2(sq, va);
        mx0 = fmaxf(mx0, lo32(va)); mx1 = fmaxf(mx1, hi32(va));
        mn0 = fminf(mn0, lo32(va)); mn1 = fminf(mn1, hi32(va));
        add2(sum, vb); fma2(sq, vb);
        mx0 = fmaxf(mx0, lo32(vb)); mx1 = fmaxf(mx1, hi32(vb));
        mn0 = fminf(mn0, lo32(vb)); mn1 = fminf(mn1, hi32(vb));
        add2(sum, vc); fma2(sq, vc);
        mx0 = fmaxf(mx0, lo32(vc)); mx1 = fmaxf(mx1, hi32(vc));
        mn0 = fminf(mn0, lo32(vc)); mn1 = fminf(mn1, hi32(vc));
        add2(sum, vd); fma2(sq, vd);
        mx0 = fmaxf(mx0, lo32(vd)); mx1 = fmaxf(mx1, hi32(vd));
        mn0 = fminf(mn0, lo32(vd)); mn1 = fminf(mn1, hi32(vd));
    }
    for (; e < d; e++) {
        int sa = g_esrc[start + e];
        ull va = hl[sa * 32];
        add2(sum, va); fma2(sq, va);
        mx0 = fmaxf(mx0, lo32(va)); mx1 = fmaxf(mx1, hi32(va));
        mn0 = fminf(mn0, lo32(va)); mn1 = fminf(mn1, hi32(va));
    }

    float* base = g_agg + (size_t)warp * 256;
    if (d > 0) {
        float inv = 1.0f / (float)d;
        float s0 = lo32(sum), s1 = hi32(sum);
        float q0 = lo32(sq),  q1 = hi32(sq);
        float mean0 = s0 * inv, mean1 = s1 * inv;
        float var0 = fmaxf(q0 * inv - mean0 * mean0, 0.f);
        float var1 = fmaxf(q1 * inv - mean1 * mean1, 0.f);
        float std0 = sqrtf(var0 + EPS_STD);
        float std1 = sqrtf(var1 + EPS_STD);
        *(float2*)(base +       2 * lane) = make_float2(mean0, mean1);
        *(float2*)(base +  64 + 2 * lane) = make_float2(mx0, mx1);
        *(float2*)(base + 128 + 2 * lane) = make_float2(mn0, mn1);
        *(float2*)(base + 192 + 2 * lane) = make_float2(std0, std1);
        if (lane == 0) {
            float logD = logf((float)d + 1.0f);
            g_c1[warp] = logD / AVG_D_LOG;
            g_c2[warp] = AVG_D_LOG / fmaxf(logD, 1e-12f);
        }
    } else {
        float2 z = make_float2(0.f, 0.f);
        *(float2*)(base +       2 * lane) = z;
        *(float2*)(base +  64 + 2 * lane) = z;
        *(float2*)(base + 128 + 2 * lane) = z;
        *(float2*)(base + 192 + 2 * lane) = z;
        if (lane == 0) { g_c1[warp] = 0.f; g_c2[warp] = 0.f; }
    }
    if (lane == 0) g_deg[warp] = 0;
}

// ---------------- K5: mma.sync bf16-split GEMM + fused BN column stats ------------
#define AST 144
#define SA_HI 0
#define SA_LO (128 * AST)
#define SB    (2 * 128 * AST)
#define SBUF  (64 * AST)
#define SMEM_MM (SB + 6 * SBUF)

__global__ void __launch_bounds__(256)
k_gemm_mma(const float* __restrict__ bias) {
    extern __shared__ char smem[];
    const uint32_t sb = smem_u32(smem);
    int t = threadIdx.x;
    int w = t >> 5;
    int lane = t & 31;
    int m0 = blockIdx.x * 128;

    float acc[3][8][4];
    #pragma unroll
    for (int p = 0; p < 3; p++)
        #pragma unroll
        for (int nt = 0; nt < 8; nt++)
            #pragma unroll
            for (int j = 0; j < 4; j++) acc[p][nt][j] = 0.f;

    for (int c = 0; c < 4; c++) {
        __syncthreads();
        #pragma unroll
        for (int it = 0; it < 4; it++) {
            int idx = t + it * 256;
            int row = idx >> 3;
            int g = idx & 7;
            int gm = m0 + row;
            uint4 hi = make_uint4(0, 0, 0, 0);
            uint4 lo = make_uint4(0, 0, 0, 0);
            if (gm < N_NODES) {
                const float* srcp = g_agg + (size_t)gm * 256 + c * 64 + g * 8;
                float4 v0 = *(const float4*)srcp;
                float4 v1 = *(const float4*)(srcp + 4);
                hi.x = packbf(v0.x, v0.y); hi.y = packbf(v0.z, v0.w);
                hi.z = packbf(v1.x, v1.y); hi.w = packbf(v1.z, v1.w);
                lo.x = packbf(bferr(v0.x), bferr(v0.y));
                lo.y = packbf(bferr(v0.z), bferr(v0.w));
                lo.z = packbf(bferr(v1.x), bferr(v1.y));
                lo.w = packbf(bferr(v1.z), bferr(v1.w));
            }
            int off = row * AST + g * 16;
            *(uint4*)(smem + SA_HI + off) = hi;
            *(uint4*)(smem + SA_LO + off) = lo;
        }
        #pragma unroll
        for (int it = 0; it < 12; it++) {
            int idx = t + it * 256;
            int buf = idx >> 9;
            int rem = idx & 511;
            int row = rem >> 3;
            int g = rem & 7;
            int p = buf >> 1;
            const __nv_bfloat16* srcp = ((buf & 1) ? g_wlo : g_whi)
                                        + row * 768 + p * 256 + c * 64 + g * 8;
            *(uint4*)(smem + SB + buf * SBUF + row * AST + g * 16) =
                *(const uint4*)srcp;
        }
        __syncthreads();

        #pragma unroll
        for (int ks = 0; ks < 4; ks++) {
            int arow = w * 16 + (lane & 15);
            uint32_t aoff = (uint32_t)(arow * AST + ks * 32 + ((lane >> 4) << 4));
            uint32_t ah0, ah1, ah2, ah3, al0, al1, al2, al3;
            ldsm4(ah0, ah1, ah2, ah3, sb + SA_HI + aoff);
            ldsm4(al0, al1, al2, al3, sb + SA_LO + aoff);

            #pragma unroll
            for (int np = 0; np < 4; np++) {
                int nrow = np * 16 + (lane & 7) + ((lane & 16) ? 8 : 0);
                uint32_t boff = (uint32_t)(nrow * AST + ks * 32 + ((lane & 8) ? 16 : 0));
                #pragma unroll
                for (int p = 0; p < 3; p++) {
                    uint32_t bh0, bh1, bh2, bh3, bl0, bl1, bl2, bl3;
                    ldsm4(bh0, bh1, bh2, bh3, sb + SB + (2 * p)     * SBUF + boff);
                    ldsm4(bl0, bl1, bl2, bl3, sb + SB + (2 * p + 1) * SBUF + boff);
                    float* d0 = acc[p][np * 2];
                    float* d1 = acc[p][np * 2 + 1];
                    mma_bf16(d0, ah0, ah1, ah2, ah3, bh0, bh1);
                    mma_bf16(d0, ah0, ah1, ah2, ah3, bl0, bl1);
                    mma_bf16(d0, al0, al1, al2, al3, bh0, bh1);
                    mma_bf16(d1, ah0, ah1, ah2, ah3, bh2, bh3);
                    mma_bf16(d1, ah0, ah1, ah2, ah3, bl2, bl3);
                    mma_bf16(d1, al0, al1, al2, al3, bh2, bh3);
                }
            }
        }
    }

    __syncthreads();
    float* swsum = (float*)smem;
    float* swsq  = (float*)(smem + 2048);

    int rowA = m0 + w * 16 + (lane >> 2);
    int rowB = rowA + 8;
    bool va = rowA < N_NODES, vb = rowB < N_NODES;
    float c1a = 0.f, c2a = 0.f, c1b = 0.f, c2b = 0.f;
    if (va) { c1a = g_c1[rowA]; c2a = g_c2[rowA]; }
    if (vb) { c1b = g_c1[rowB]; c2b = g_c2[rowB]; }

    #pragma unroll
    for (int nt = 0; nt < 8; nt++) {
        int col = nt * 8 + (lane & 3) * 2;
        float b0 = bias[col];
        float b1 = bias[col + 1];
        float x0a = acc[0][nt][0] + c1a * acc[1][nt][0] + c2a * acc[2][nt][0] + b0;
        float x1a = acc[0][nt][1] + c1a * acc[1][nt][1] + c2a * acc[2][nt][1] + b1;
        float x0b = acc[0][nt][2] + c1b * acc[1][nt][2] + c2b * acc[2][nt][2] + b0;
        float x1b = acc[0][nt][3] + c1b * acc[1][nt][3] + c2b * acc[2][nt][3] + b1;
        if (va) *(float2*)(g_x + (size_t)rowA * 64 + col) = make_float2(x0a, x1a);
        if (vb) *(float2*)(g_x + (size_t)rowB * 64 + col) = make_float2(x0b, x1b);

        float s0 = (va ? x0a : 0.f) + (vb ? x0b : 0.f);
        float s1 = (va ? x1a : 0.f) + (vb ? x1b : 0.f);
        float q0 = (va ? x0a * x0a : 0.f) + (vb ? x0b * x0b : 0.f);
        float q1 = (va ? x1a * x1a : 0.f) + (vb ? x1b * x1b : 0.f);
        #pragma unroll
        for (int o = 4; o <= 16; o <<= 1) {
            s0 += __shfl_xor_sync(0xffffffffu, s0, o);
            s1 += __shfl_xor_sync(0xffffffffu, s1, o);
            q0 += __shfl_xor_sync(0xffffffffu, q0, o);
            q1 += __shfl_xor_sync(0xffffffffu, q1, o);
        }
        if (lane < 4) {
            swsum[w * 64 + nt * 8 + lane * 2]     = s0;
            swsum[w * 64 + nt * 8 + lane * 2 + 1] = s1;
            swsq [w * 64 + nt * 8 + lane * 2]     = q0;
            swsq [w * 64 + nt * 8 + lane * 2 + 1] = q1;
        }
    }
    __syncthreads();
    if (t < 64) {
        float s = 0.f, q = 0.f;
        #pragma unroll
        for (int k = 0; k < 8; k++) {
            s += swsum[k * 64 + t];
            q += swsq[k * 64 + t];
        }
        atomicAdd(&g_colsum[t], s);
        atomicAdd(&g_colsq[t], q);
    }
}

// ---------------- K6: BN + ReLU + residual (float4) -------------------------------
__global__ void k_final(const float* __restrict__ h,
                        const float* __restrict__ gamma,
                        const float* __restrict__ beta,
                        float* __restrict__ out) {
    int i = blockIdx.x * blockDim.x + threadIdx.x;   // float4 index
    if (i >= N_NODES * F_DIM / 4) return;
    int j = (i & 15) * 4;                            // col of first lane elem
    const float invN = 1.0f / (float)N_NODES;
    float4 cs = *(const float4*)(g_colsum + j);
    float4 cq = *(const float4*)(g_colsq + j);
    float4 gm = *(const float4*)(gamma + j);
    float4 bt = *(const float4*)(beta + j);
    float4 xv = ((const float4*)g_x)[i];
    float4 hv = ((const float4*)h)[i];
    float4 r;
    {
        float mu = cs.x * invN;
        float inv = rsqrtf(cq.x * invN - mu * mu + EPS_BN);
        r.x = hv.x + fmaxf(gm.x * (xv.x - mu) * inv + bt.x, 0.f);
    }
    {
        float mu = cs.y * invN;
        float inv = rsqrtf(cq.y * invN - mu * mu + EPS_BN);
        r.y = hv.y + fmaxf(gm.y * (xv.y - mu) * inv + bt.y, 0.f);
    }
    {
        float mu = cs.z * invN;
        float inv = rsqrtf(cq.z * invN - mu * mu + EPS_BN);
        r.z = hv.z + fmaxf(gm.z * (xv.z - mu) * inv + bt.z, 0.f);
    }
    {
        float mu = cs.w * invN;
        float inv = rsqrtf(cq.w * invN - mu * mu + EPS_BN);
        r.w = hv.w + fmaxf(gm.w * (xv.w - mu) * inv + bt.w, 0.f);
    }
    ((float4*)out)[i] = r;
}

// ---------------- launch ------------------------------------------------------------
extern "C" void kernel_launch(void* const* d_in, const int* in_sizes, int n_in,
                              void* d_out, int out_size) {
    const float* h     = (const float*)d_in[0];
    const int*   src   = (const int*)d_in[1];
    const int*   dst   = (const int*)d_in[2];
    const float* W     = (const float*)d_in[3];
    const float* b     = (const float*)d_in[4];
    const float* gamma = (const float*)d_in[5];
    const float* beta  = (const float*)d_in[6];
    float* out = (float*)d_out;

    cudaFuncSetAttribute(k_gemm_mma, cudaFuncAttributeMaxDynamicSharedMemorySize, SMEM_MM);

    k_hist_wprep<<<(N_EDGES / 4 + 255) / 256, 256>>>(dst, W);
    k_scan<<<NB, 256>>>();
    k_scatter<<<(N_EDGES / 4 + 255) / 256, 256>>>(src, dst);
    k_agg<<<(N_NODES + 7) / 8, 256>>>(h);
    k_gemm_mma<<<(N_NODES + 127) / 128, 256, SMEM_MM>>>(b);
    k_final<<<(N_NODES * F_DIM / 4 + 255) / 256, 256>>>(h, gamma, beta, out);
}